// round 2
// baseline (speedup 1.0000x reference)
#include <cuda_runtime.h>
#include <math.h>

// ---------------- problem constants ----------------
#define NN   512
#define BB   2
#define DD   128
#define OO   16
#define HH   64
#define CH   48
#define CUMSZ (513*256)           // [513][B][D]
#define SPRE_SZ (2*16*512*512)    // [B][O][512][512]
#define H1_SZ   (2*48*514*514)    // [B][CH][514][514]
#define S_OUT_SZ (512*512*2*16)   // 8388608
#define PAIR_ROWS (131328*2)      // 262656
#define SKIP_ROWS (511*2)         // 1022

__device__ float g_cum[3*CUMSZ];
__device__ float g_Spre[SPRE_SZ];
__device__ float g_H1[H1_SZ];

__device__ __forceinline__ float gelu_f(float v) {
    return 0.5f*v*(1.0f + erff(v*0.70710678118654752440f));
}

// ---------------- prefix sums of x, x^2, x^3 ----------------
__global__ void prefix_kernel(const float* __restrict__ x) {
    int t = threadIdx.x;              // 256 = B*D columns
    float s1 = 0.f, s2 = 0.f, s3 = 0.f;
    g_cum[t] = 0.f; g_cum[CUMSZ + t] = 0.f; g_cum[2*CUMSZ + t] = 0.f;
    for (int n = 0; n < NN; ++n) {
        float v = x[n*256 + t];
        float v2 = v*v;
        s1 += v; s2 += v2; s3 += v2*v;
        int o = (n+1)*256 + t;
        g_cum[o] = s1; g_cum[CUMSZ + o] = s2; g_cum[2*CUMSZ + o] = s3;
    }
}

// ---------------- zero the scatter target ----------------
__global__ void zero_spre_kernel() {
    int i = blockIdx.x*blockDim.x + threadIdx.x;
    ((float4*)g_Spre)[i] = make_float4(0.f, 0.f, 0.f, 0.f);
}

// ---------------- fused feature-gen + 3-layer MLP (tiled GEMM) ----------------
// 64 rows per block, 256 threads, 16x16 thread grid, 4x4 micro-tile.
template<int KIN, bool IS_SKIP>
__global__ __launch_bounds__(256) void mlp_kernel(
    const float* __restrict__ x,
    const float* __restrict__ w1, const float* __restrict__ b1,
    const float* __restrict__ w2, const float* __restrict__ b2,
    const float* __restrict__ w3, const float* __restrict__ b3,
    float* __restrict__ outSkip, int nrows)
{
    __shared__ float sAB[64*68];   // A-tile [32][68] + B-tile [32][68]; also w2 [64][68] / w3 [64][16]
    __shared__ float sH [64*68];   // hidden activations, [unit][row]
    __shared__ int   sXI[64], sXJ[64], sCI[64], sCJ[64], sOut[64];
    __shared__ float sInv[64], sb1[64], sb2[64], sb3[16];

    const int tid = threadIdx.x;
    const int ty4 = (tid >> 4) * 4;
    const int tx4 = (tid & 15) * 4;

    if (tid < 64) {
        int r = blockIdx.x*64 + tid;
        if (IS_SKIP && r >= nrows) r = nrows - 1;
        int p = r >> 1, b = r & 1;
        if (!IS_SKIP) {
            int i = (int)((sqrt(8.0*(double)p + 1.0) - 1.0)*0.5);
            while ((i+1)*(i+2)/2 <= p) ++i;
            while (i*(i+1)/2 > p) --i;
            int j = p - i*(i+1)/2;
            sXI[tid]  = i*256 + b*128;
            sXJ[tid]  = j*256 + b*128;
            sCI[tid]  = (i+1)*256 + b*128;
            sCJ[tid]  = j*256 + b*128;
            sInv[tid] = 1.0f/(float)(i - j + 1);
            sOut[tid] = b*4194304 + i*512 + j;   // b*16*512*512 base; + o*262144 later
        } else {
            sXI[tid]  = p*256 + b*128;           // x[t]
            sXJ[tid]  = (p+1)*256 + b*128;       // x[t+1]
            sInv[tid] = 1.0f;
            sOut[tid] = r*16;
        }
        sb1[tid] = b1[tid];
        sb2[tid] = b2[tid];
        if (tid < 16) sb3[tid] = b3[tid];
    }
    __syncthreads();

    // -------- layer 1: [64 x KIN] @ w1^T -> [64 x 64] --------
    float acc[4][4] = {};
    const int NCH = KIN/32;
    for (int kc = 0; kc < NCH; ++kc) {
        const int k0  = kc*32;
        const int seg = k0 >> 7;
        const int d0  = k0 & 127;
        #pragma unroll
        for (int e = 0; e < 8; ++e) {             // generate A chunk [64 rows][32 k]
            int idx = tid + e*256;
            int row = idx >> 5, kk = idx & 31;
            int d = d0 + kk;
            float v;
            if (seg == 0)      v = x[sXI[row] + d];
            else if (seg == 1) v = x[sXJ[row] + d];
            else if (seg == 2) v = x[sXI[row] + d] * x[sXJ[row] + d];
            else {
                const float* c0 = g_cum + (seg-3)*CUMSZ;
                v = (c0[sCI[row] + d] - c0[sCJ[row] + d]) * sInv[row];
            }
            sAB[kk*68 + row] = v;
        }
        #pragma unroll
        for (int e = 0; e < 8; ++e) {             // load w1 chunk, transposed
            int idx = tid + e*256;
            int col = idx >> 5, kk = idx & 31;
            sAB[(32+kk)*68 + col] = w1[col*KIN + k0 + kk];
        }
        __syncthreads();
        #pragma unroll
        for (int kk = 0; kk < 32; ++kk) {
            float4 a  = *(const float4*)&sAB[kk*68 + ty4];
            float4 bv = *(const float4*)&sAB[(32+kk)*68 + tx4];
            acc[0][0] += a.x*bv.x; acc[0][1] += a.x*bv.y; acc[0][2] += a.x*bv.z; acc[0][3] += a.x*bv.w;
            acc[1][0] += a.y*bv.x; acc[1][1] += a.y*bv.y; acc[1][2] += a.y*bv.z; acc[1][3] += a.y*bv.w;
            acc[2][0] += a.z*bv.x; acc[2][1] += a.z*bv.y; acc[2][2] += a.z*bv.z; acc[2][3] += a.z*bv.w;
            acc[3][0] += a.w*bv.x; acc[3][1] += a.w*bv.y; acc[3][2] += a.w*bv.z; acc[3][3] += a.w*bv.w;
        }
        __syncthreads();
    }
    // bias + gelu -> sH [unit][row]
    #pragma unroll
    for (int c = 0; c < 4; ++c) {
        float bias = sb1[tx4 + c];
        #pragma unroll
        for (int r = 0; r < 4; ++r)
            sH[(tx4 + c)*68 + ty4 + r] = gelu_f(acc[r][c] + bias);
    }
    // -------- layer 2: [64 x 64] @ w2^T -> [64 x 64] --------
    #pragma unroll
    for (int e = 0; e < 16; ++e) {
        int idx = tid + e*256;
        int col = idx >> 6, kk = idx & 63;
        sAB[kk*68 + col] = w2[col*64 + kk];
    }
    __syncthreads();
    float acc2[4][4] = {};
    #pragma unroll
    for (int kk = 0; kk < 64; ++kk) {
        float4 a  = *(const float4*)&sH [kk*68 + ty4];
        float4 bv = *(const float4*)&sAB[kk*68 + tx4];
        acc2[0][0] += a.x*bv.x; acc2[0][1] += a.x*bv.y; acc2[0][2] += a.x*bv.z; acc2[0][3] += a.x*bv.w;
        acc2[1][0] += a.y*bv.x; acc2[1][1] += a.y*bv.y; acc2[1][2] += a.y*bv.z; acc2[1][3] += a.y*bv.w;
        acc2[2][0] += a.z*bv.x; acc2[2][1] += a.z*bv.y; acc2[2][2] += a.z*bv.z; acc2[2][3] += a.z*bv.w;
        acc2[3][0] += a.w*bv.x; acc2[3][1] += a.w*bv.y; acc2[3][2] += a.w*bv.z; acc2[3][3] += a.w*bv.w;
    }
    __syncthreads();
    #pragma unroll
    for (int c = 0; c < 4; ++c) {
        float bias = sb2[tx4 + c];
        #pragma unroll
        for (int r = 0; r < 4; ++r)
            sH[(tx4 + c)*68 + ty4 + r] = gelu_f(acc2[r][c] + bias);
    }
    // -------- layer 3: [64 x 64] @ w3^T -> [64 x 16] --------
    #pragma unroll
    for (int e = 0; e < 4; ++e) {
        int idx = tid + e*256;                  // 1024 elems
        int col = idx >> 6, kk = idx & 63;
        sAB[kk*16 + col] = w3[col*64 + kk];
    }
    __syncthreads();
    const int row = tid >> 2;
    const int cg  = (tid & 3)*4;
    float o4[4] = {};
    #pragma unroll
    for (int kk = 0; kk < 64; ++kk) {
        float a   = sH[kk*68 + row];
        float4 wv = *(const float4*)&sAB[kk*16 + cg];
        o4[0] += a*wv.x; o4[1] += a*wv.y; o4[2] += a*wv.z; o4[3] += a*wv.w;
    }
    if (!IS_SKIP) {
        int base = sOut[row];
        #pragma unroll
        for (int c = 0; c < 4; ++c)
            g_Spre[base + (cg + c)*262144] = o4[c] + sb3[cg + c];
    } else {
        int rg = blockIdx.x*64 + row;
        if (rg < nrows) {
            int base = sOut[row];
            #pragma unroll
            for (int c = 0; c < 4; ++c)
                outSkip[base + cg + c] = o4[c] + sb3[cg + c];
        }
    }
}

// ---------------- conv1: 16 -> 48, 3x3, pad 2, + GELU ----------------
// grid (9, 33, 8): z = b*4 + oc-group(12). Tile 16y x 64x, thread does 4 x-pixels.
__global__ __launch_bounds__(256) void conv1_kernel(
    const float* __restrict__ cw1, const float* __restrict__ cb1)
{
    extern __shared__ float smem[];
    float* sIn = smem;                 // [16][18][67]
    float* sW  = smem + 16*18*67;      // [12][16][9]
    const int tid = threadIdx.x;
    const int b = blockIdx.z >> 2, g = blockIdx.z & 3;
    const int by = blockIdx.y, bx = blockIdx.x;
    const int ty = tid >> 4, tx = tid & 15;

    for (int idx = tid; idx < 16*18*66; idx += 256) {
        int c  = idx / 1188;
        int rem = idx - c*1188;
        int sy = rem / 66, sx = rem - sy*66;
        int iy = by*16 + sy - 2;
        int ix = bx*64 + sx - 2;
        float v = 0.f;
        if (iy >= 0 && iy < 512 && ix >= 0 && ix < 512)
            v = g_Spre[((b*16 + c) << 18) + (iy << 9) + ix];
        sIn[(c*18 + sy)*67 + sx] = v;
    }
    for (int idx = tid; idx < 12*16*9; idx += 256)
        sW[idx] = cw1[g*12*144 + idx];
    __syncthreads();

    float acc[12][4] = {};
    #pragma unroll 1
    for (int c = 0; c < 16; ++c) {
        #pragma unroll
        for (int ky = 0; ky < 3; ++ky) {
            const float* rp = &sIn[(c*18 + ty + ky)*67 + tx*4];
            float vv[6];
            #pragma unroll
            for (int m = 0; m < 6; ++m) vv[m] = rp[m];
            #pragma unroll
            for (int kx = 0; kx < 3; ++kx) {
                #pragma unroll
                for (int oc = 0; oc < 12; ++oc) {
                    float w = sW[(oc*16 + c)*9 + ky*3 + kx];
                    acc[oc][0] += w*vv[kx+0];
                    acc[oc][1] += w*vv[kx+1];
                    acc[oc][2] += w*vv[kx+2];
                    acc[oc][3] += w*vv[kx+3];
                }
            }
        }
    }
    int oy = by*16 + ty;
    if (oy < 514) {
        #pragma unroll
        for (int oc = 0; oc < 12; ++oc) {
            int oco = g*12 + oc;
            float bias = cb1[oco];
            int base = ((b*48 + oco)*514 + oy)*514;
            #pragma unroll
            for (int px = 0; px < 4; ++px) {
                int ox = bx*64 + tx*4 + px;
                if (ox < 514) g_H1[base + ox] = gelu_f(acc[oc][px] + bias);
            }
        }
    }
}

// ---------------- conv2: 48 -> 16, 3x3 valid, + bias + length-scale + store ----------------
// grid (8, 32, 2): z = b. Tile 16y x 64x of 512x512.
__global__ __launch_bounds__(256) void conv2_kernel(
    const float* __restrict__ cw2, const float* __restrict__ cb2,
    float* __restrict__ out)
{
    extern __shared__ float smem[];
    float* sIn = smem;                 // [12][18][67]
    float* sW  = smem + 12*18*67;      // [16][48][9]
    const int tid = threadIdx.x;
    const int b = blockIdx.z;
    const int by = blockIdx.y, bx = blockIdx.x;
    const int ty = tid >> 4, tx = tid & 15;

    for (int idx = tid; idx < 16*48*9; idx += 256) sW[idx] = cw2[idx];

    float acc[16][4] = {};
    for (int cc = 0; cc < 4; ++cc) {
        __syncthreads();
        for (int idx = tid; idx < 12*18*66; idx += 256) {
            int c  = idx / 1188;
            int rem = idx - c*1188;
            int sy = rem / 66, sx = rem - sy*66;
            sIn[(c*18 + sy)*67 + sx] =
                g_H1[((b*48 + cc*12 + c)*514 + by*16 + sy)*514 + bx*64 + sx];
        }
        __syncthreads();
        #pragma unroll 1
        for (int c = 0; c < 12; ++c) {
            #pragma unroll
            for (int ky = 0; ky < 3; ++ky) {
                const float* rp = &sIn[(c*18 + ty + ky)*67 + tx*4];
                float vv[6];
                #pragma unroll
                for (int m = 0; m < 6; ++m) vv[m] = rp[m];
                #pragma unroll
                for (int kx = 0; kx < 3; ++kx) {
                    #pragma unroll
                    for (int oc = 0; oc < 16; ++oc) {
                        float w = sW[(oc*48 + cc*12 + c)*9 + ky*3 + kx];
                        acc[oc][0] += w*vv[kx+0];
                        acc[oc][1] += w*vv[kx+1];
                        acc[oc][2] += w*vv[kx+2];
                        acc[oc][3] += w*vv[kx+3];
                    }
                }
            }
        }
    }
    int oy = by*16 + ty;
    #pragma unroll
    for (int px = 0; px < 4; ++px) {
        int ox = bx*64 + tx*4 + px;
        int ad = oy - ox; if (ad < 0) ad = -ad; if (ad < 1) ad = 1;
        float len = (float)ad;
        int base = ((oy*512 + ox)*2 + b)*16;
        #pragma unroll
        for (int oc = 0; oc < 16; ++oc)
            out[base + oc] = len*(acc[oc][px] + cb2[oc]);
    }
}

// ---------------- launch ----------------
extern "C" void kernel_launch(void* const* d_in, const int* in_sizes, int n_in,
                              void* d_out, int out_size)
{
    const float* x   = (const float*)d_in[0];
    const float* w1  = (const float*)d_in[1];
    const float* b1  = (const float*)d_in[2];
    const float* w2  = (const float*)d_in[3];
    const float* b2  = (const float*)d_in[4];
    const float* w3  = (const float*)d_in[5];
    const float* b3  = (const float*)d_in[6];
    const float* sw1 = (const float*)d_in[7];
    const float* sb1 = (const float*)d_in[8];
    const float* sw2 = (const float*)d_in[9];
    const float* sb2 = (const float*)d_in[10];
    const float* sw3 = (const float*)d_in[11];
    const float* sb3 = (const float*)d_in[12];
    const float* cw1 = (const float*)d_in[13];
    const float* cb1 = (const float*)d_in[14];
    const float* cw2 = (const float*)d_in[15];
    const float* cb2 = (const float*)d_in[16];
    float* out = (float*)d_out;

    static bool attr_done = false;
    if (!attr_done) {
        cudaFuncSetAttribute(conv1_kernel, cudaFuncAttributeMaxDynamicSharedMemorySize, (16*18*67 + 12*16*9)*4);
        cudaFuncSetAttribute(conv2_kernel, cudaFuncAttributeMaxDynamicSharedMemorySize, (12*18*67 + 16*48*9)*4);
        attr_done = true;
    }

    zero_spre_kernel<<<SPRE_SZ/4/256, 256>>>();
    prefix_kernel<<<1, 256>>>(x);
    mlp_kernel<768, false><<<PAIR_ROWS/64, 256>>>(x, w1, b1, w2, b2, w3, b3, nullptr, PAIR_ROWS);
    mlp_kernel<384, true ><<<(SKIP_ROWS + 63)/64, 256>>>(x, sw1, sb1, sw2, sb2, sw3, sb3, out + S_OUT_SZ, SKIP_ROWS);
    conv1_kernel<<<dim3(9, 33, 8), 256, (16*18*67 + 12*16*9)*4>>>(cw1, cb1);
    conv2_kernel<<<dim3(8, 32, 2), 256, (12*18*67 + 16*48*9)*4>>>(cw2, cb2, out);
}